// round 9
// baseline (speedup 1.0000x reference)
#include <cuda_runtime.h>
#include <cuda_fp16.h>
#include <cstdint>

#define BB 4
#define SS 4096
#define DD 128
#define MTOT (BB*SS)

#define BM 64
#define BN 64

// Q scale: 1/sqrt(128) * log2(e)  (softmax uses ex2 directly)
#define QSCALE 0.12751743f

// fp16 scratch
__device__ __half g_qh[MTOT*DD];   // Q, pre-scaled by QSCALE
__device__ __half g_kh[MTOT*DD];   // K
__device__ __half g_vh[MTOT*DD];   // V
__device__ __half g_wh[3*DD*DD];   // W hi split
__device__ __half g_wl[3*DD*DD];   // W lo split

// ---------------------------------------------------------------------------
// helpers
// ---------------------------------------------------------------------------
__device__ __forceinline__ uint32_t smem_u32(const void* p) {
    uint32_t a;
    asm("{ .reg .u64 t; cvta.to.shared.u64 t, %1; cvt.u32.u64 %0, t; }"
        : "=r"(a) : "l"(p));
    return a;
}
__device__ __forceinline__ void cp16(uint32_t d, const void* s) {
    asm volatile("cp.async.cg.shared.global [%0], [%1], 16;" :: "r"(d), "l"(s));
}
#define CP_COMMIT() asm volatile("cp.async.commit_group;" ::: "memory")
#define CP_WAIT(N)  asm volatile("cp.async.wait_group %0;" :: "n"(N) : "memory")

__device__ __forceinline__ void ldsm4(uint32_t& r0, uint32_t& r1,
                                      uint32_t& r2, uint32_t& r3, uint32_t a) {
    asm volatile("ldmatrix.sync.aligned.m8n8.x4.shared.b16 {%0,%1,%2,%3},[%4];"
                 : "=r"(r0),"=r"(r1),"=r"(r2),"=r"(r3) : "r"(a));
}
__device__ __forceinline__ void ldsm4t(uint32_t& r0, uint32_t& r1,
                                       uint32_t& r2, uint32_t& r3, uint32_t a) {
    asm volatile("ldmatrix.sync.aligned.m8n8.x4.trans.shared.b16 {%0,%1,%2,%3},[%4];"
                 : "=r"(r0),"=r"(r1),"=r"(r2),"=r"(r3) : "r"(a));
}
__device__ __forceinline__ void mma16816(float* c, const uint32_t* a,
                                         uint32_t b0, uint32_t b1) {
    asm volatile("mma.sync.aligned.m16n8k16.row.col.f32.f16.f16.f32 "
                 "{%0,%1,%2,%3},{%4,%5,%6,%7},{%8,%9},{%0,%1,%2,%3};"
                 : "+f"(c[0]),"+f"(c[1]),"+f"(c[2]),"+f"(c[3])
                 : "r"(a[0]),"r"(a[1]),"r"(a[2]),"r"(a[3]),"r"(b0),"r"(b1));
}
__device__ __forceinline__ uint32_t packh2(float x, float y) {
    __half2 h = __floats2half2_rn(x, y);
    return *(uint32_t*)&h;
}
__device__ __forceinline__ float ex2f(float x) {
    float r;
    asm("ex2.approx.f32 %0, %1;" : "=f"(r) : "f"(x));
    return r;
}
__device__ __forceinline__ void split2(float a, float b, uint32_t& h, uint32_t& l) {
    __half ha = __float2half_rn(a), hb = __float2half_rn(b);
    __half la = __float2half_rn(a - __half2float(ha));
    __half lb = __float2half_rn(b - __half2float(hb));
    __half2 H = __halves2half2(ha, hb), L = __halves2half2(la, lb);
    h = *(uint32_t*)&H; l = *(uint32_t*)&L;
}

// ---------------------------------------------------------------------------
// Kernel 0: split W into (hi, lo) fp16 pairs. grid 48 x 256.
// ---------------------------------------------------------------------------
__global__ __launch_bounds__(256) void split_w(
    const float* __restrict__ Wq,
    const float* __restrict__ Wk,
    const float* __restrict__ Wv)
{
    int j = blockIdx.x*256 + threadIdx.x;      // float4 index, 12288 total
    int wsel = j >> 12, off = j & 4095;
    const float* W = (wsel==0) ? Wq : (wsel==1) ? Wk : Wv;
    float4 v = ((const float4*)W)[off];
    uint2 ho, lo;
    split2(v.x, v.y, ho.x, lo.x);
    split2(v.z, v.w, ho.y, lo.y);
    ((uint2*)(g_wh + wsel*DD*DD))[off] = ho;
    ((uint2*)(g_wl + wsel*DD*DD))[off] = lo;
}

// ---------------------------------------------------------------------------
// Kernel 1: QKV projection via mma.sync fp16 3-term split; x split in-kernel.
// grid (256, 3), 128 threads. y = x @ W^T.
// ---------------------------------------------------------------------------
#define PJ_XH 0
#define PJ_XL 16384
#define PJ_WH 32768
#define PJ_WL 65536
#define PJ_SMEM 98304

__global__ __launch_bounds__(128) void proj_mma(const float* __restrict__ x)
{
    extern __shared__ char smem[];
    const uint32_t sb = smem_u32(smem);
    const int tid = threadIdx.x, wid = tid>>5, lane = tid&31;
    const int m0 = blockIdx.x * 64;
    const int psel = blockIdx.y;

    const __half* Wh = g_wh + psel*DD*DD;
    const __half* Wl = g_wl + psel*DD*DD;

    // stage Wh/Wl (128x128) via cp.async
    for (int i = tid; i < 2048; i += 128) {
        int r = i>>4, c = i&15;
        uint32_t off = r*256 + ((c ^ (r&7))<<4);
        cp16(sb + PJ_WH + off, Wh + (size_t)r*DD + c*8);
        cp16(sb + PJ_WL + off, Wl + (size_t)r*DD + c*8);
    }
    CP_COMMIT();
    // stage + split x (64x128 fp32) inline
    for (int i = tid; i < 1024; i += 128) {
        int r = i>>4, c = i&15;
        const float* src = x + (size_t)(m0+r)*DD + c*8;
        float4 v0 = *(const float4*)src;
        float4 v1 = *(const float4*)(src+4);
        uint4 hi, lo;
        split2(v0.x, v0.y, hi.x, lo.x);
        split2(v0.z, v0.w, hi.y, lo.y);
        split2(v1.x, v1.y, hi.z, lo.z);
        split2(v1.z, v1.w, hi.w, lo.w);
        uint32_t off = r*256 + ((c ^ (r&7))<<4);
        *(uint4*)(smem + PJ_XH + off) = hi;
        *(uint4*)(smem + PJ_XL + off) = lo;
    }
    CP_WAIT(0);
    __syncthreads();

    float acc[16][4];
#pragma unroll
    for (int n=0;n<16;++n){ acc[n][0]=acc[n][1]=acc[n][2]=acc[n][3]=0.f; }

    const int arow  = wid*16 + (lane&7) + (((lane>>3)&1)<<3);
    const int achnk = lane>>4;
    const int keyr  = (lane&7) + ((lane>>4)<<3);
    const int kchnk = (lane>>3)&1;

#pragma unroll
    for (int j=0;j<8;++j) {
        uint32_t ah[4], al[4];
        {
            uint32_t cc = 2*j + achnk;
            uint32_t off = arow*256 + ((cc ^ (arow&7))<<4);
            ldsm4(ah[0],ah[1],ah[2],ah[3], sb + PJ_XH + off);
            ldsm4(al[0],al[1],al[2],al[3], sb + PJ_XL + off);
        }
#pragma unroll
        for (int np=0;np<8;++np) {
            int key = np*16 + keyr;
            uint32_t cc = 2*j + kchnk;
            uint32_t off = key*256 + ((cc ^ (key&7))<<4);
            uint32_t b0,b1,b2,b3, c0,c1,c2,c3;
            ldsm4(b0,b1,b2,b3, sb + PJ_WH + off);
            ldsm4(c0,c1,c2,c3, sb + PJ_WL + off);
            mma16816(acc[2*np],   ah, b0, b1);
            mma16816(acc[2*np+1], ah, b2, b3);
            mma16816(acc[2*np],   al, b0, b1);
            mma16816(acc[2*np+1], al, b2, b3);
            mma16816(acc[2*np],   ah, c0, c1);
            mma16816(acc[2*np+1], ah, c2, c3);
        }
    }

    const float sc = (psel==0) ? QSCALE : 1.0f;
    __half* outp = (psel==0) ? g_qh : (psel==1) ? g_kh : g_vh;
    const int g  = lane>>2;
    const int t2 = (lane&3)*2;
    __half* o0 = outp + (size_t)(m0 + wid*16 + g)*DD;
    __half* o1 = o0 + 8*DD;
#pragma unroll
    for (int nt=0; nt<16; ++nt) {
        *(uint32_t*)(o0 + nt*8 + t2) = packh2(acc[nt][0]*sc, acc[nt][1]*sc);
        *(uint32_t*)(o1 + nt*8 + t2) = packh2(acc[nt][2]*sc, acc[nt][3]*sc);
    }
}

// ---------------------------------------------------------------------------
// Kernel 2: fp16 flash attention, 8 warps/CTA, key-half split per warp pair.
// Warp w: qgroup = w&3 (16 q rows), khalf = w>>2 (32 of 64 keys per tile).
// O and l are partial over khalf; merged once through smem at the end
// (valid because no-max softmax is linear over key partitions).
// grid = 256 (balance-remapped), 256 threads.
// ---------------------------------------------------------------------------
#define SM_K 0
#define SM_V 32768
#define SM_Q 65536
#define SM_ATTN (65536 + 16384)

__global__ __launch_bounds__(256,2) void attn_mma(float* __restrict__ out)
{
    extern __shared__ char smem[];
    const uint32_t sb = smem_u32(smem);
    const int tid = threadIdx.x, wid = tid>>5, lane = tid&31;
    const int qg = wid & 3, kh = wid >> 2;

    // ---- load-balance remap (co-resident pairs complementary) ----
    const int bid = blockIdx.x;
    int b, qt;
    if (bid < 108)      { qt = 63 - (bid>>2);       b = bid & 3; }
    else if (bid < 148) { qt = 27 + ((bid-108)>>2); b = (bid-108) & 3; }
    else                { qt = (bid-148)>>2;        b = (bid-148) & 3; }

    const int nkt = qt + 1;
    const size_t qrow0 = (size_t)b*SS + (size_t)qt*BM;

    const int g  = lane >> 2;
    const int t2 = (lane & 3) * 2;

    const __half* kbase = g_kh + (size_t)b*SS*DD;
    const __half* vbase = g_vh + (size_t)b*SS*DD;

    // ---- prologue: Q + tile0 (group 0), tile1 (group 1) ----
    {
        const __half* qs = g_qh + qrow0*DD;
        for (int i = tid; i < 1024; i += 256) {
            int r = i>>4, c = i&15;
            uint32_t off = r*256 + ((c ^ (r&7))<<4);
            cp16(sb + SM_Q + off, qs + (size_t)r*DD + c*8);
        }
        for (int i = tid; i < 1024; i += 256) {
            int r = i>>4, c = i&15;
            uint32_t off = r*256 + ((c ^ (r&7))<<4);
            cp16(sb + SM_K + off, kbase + (size_t)r*DD + c*8);
            cp16(sb + SM_V + off, vbase + (size_t)r*DD + c*8);
        }
        CP_COMMIT();
        if (nkt > 1) {
            const __half* ks = kbase + BN*DD;
            const __half* vs = vbase + BN*DD;
            for (int i = tid; i < 1024; i += 256) {
                int r = i>>4, c = i&15;
                uint32_t off = r*256 + ((c ^ (r&7))<<4);
                cp16(sb + SM_K + 16384 + off, ks + (size_t)r*DD + c*8);
                cp16(sb + SM_V + 16384 + off, vs + (size_t)r*DD + c*8);
            }
            CP_COMMIT();
        }
    }

    float o[16][4];
#pragma unroll
    for (int d=0;d<16;++d){ o[d][0]=o[d][1]=o[d][2]=o[d][3]=0.f; }
    float lr0 = 0.f, lr1 = 0.f;

    const int arow  = qg*16 + (lane&7) + (((lane>>3)&1)<<3);
    const int achnk = lane>>4;
    const int keyr  = kh*32 + (lane&7) + ((lane>>4)<<3);
    const int kchnk = (lane>>3)&1;
    const int vrow_ = kh*32 + (lane&7) + (((lane>>3)&1)<<3);
    const int vchnk = lane>>4;

    for (int kt = 0; kt < nkt; ++kt) {
        const int buf = kt & 1;
        if (kt + 2 <= nkt) { CP_WAIT(1); } else { CP_WAIT(0); }
        __syncthreads();

        const uint32_t kb = sb + SM_K + buf*16384;
        const uint32_t vb = sb + SM_V + buf*16384;

        // ---- S = Q K^T (own 32-key half) ----
        float s[4][4];
#pragma unroll
        for (int t=0;t<4;++t){ s[t][0]=s[t][1]=s[t][2]=s[t][3]=0.f; }
#pragma unroll
        for (int j=0;j<8;++j) {
            uint32_t qa[4];
            {
                uint32_t cc = 2*j + achnk;
                uint32_t off = arow*256 + ((cc ^ (arow&7))<<4);
                ldsm4(qa[0],qa[1],qa[2],qa[3], sb + SM_Q + off);
            }
#pragma unroll
            for (int tp=0;tp<2;++tp) {
                int key = tp*16 + keyr;
                int cc  = 2*j + kchnk;
                uint32_t addr = kb + key*256 + (((cc ^ (key&7)))<<4);
                uint32_t b0,b1,b2,b3;
                ldsm4(b0,b1,b2,b3, addr);
                mma16816(s[2*tp],   qa, b0, b1);
                mma16816(s[2*tp+1], qa, b2, b3);
            }
        }

        // ---- softmax: p = 2^s ----
        uint32_t pa[2][4];
        const bool diag = (kt == qt);
        const int r0l = qg*16 + g;
#pragma unroll
        for (int t=0;t<4;++t) {
            float v0 = s[t][0], v1 = s[t][1], v2 = s[t][2], v3 = s[t][3];
            if (diag) {
                int kc = kh*32 + t*8 + t2;
                if (kc   > r0l)   v0 = -1e30f;
                if (kc+1 > r0l)   v1 = -1e30f;
                if (kc   > r0l+8) v2 = -1e30f;
                if (kc+1 > r0l+8) v3 = -1e30f;
            }
            float p0 = ex2f(v0), p1 = ex2f(v1), p2 = ex2f(v2), p3 = ex2f(v3);
            lr0 += p0 + p1;
            lr1 += p2 + p3;
            if ((t & 1) == 0) {
                pa[t>>1][0] = packh2(p0,p1);
                pa[t>>1][1] = packh2(p2,p3);
            } else {
                pa[t>>1][2] = packh2(p0,p1);
                pa[t>>1][3] = packh2(p2,p3);
            }
        }

        // ---- O += P V (own 32-key half, full d range) ----
#pragma unroll
        for (int j2=0;j2<2;++j2) {
#pragma unroll
            for (int dp=0;dp<8;++dp) {
                int row = j2*16 + vrow_;
                int cc  = dp*2 + vchnk;
                uint32_t addr = vb + row*256 + (((cc ^ (row&7)))<<4);
                uint32_t v0,v1,v2,v3;
                ldsm4t(v0,v1,v2,v3, addr);
                mma16816(o[2*dp],   pa[j2], v0, v1);
                mma16816(o[2*dp+1], pa[j2], v2, v3);
            }
        }

        __syncthreads();
        if (kt + 2 < nkt) {
            const __half* ks = kbase + (size_t)(kt+2)*BN*DD;
            const __half* vs = vbase + (size_t)(kt+2)*BN*DD;
            for (int i = tid; i < 1024; i += 256) {
                int r = i>>4, c = i&15;
                uint32_t off = r*256 + ((c ^ (r&7))<<4);
                cp16(kb + off, ks + (size_t)r*DD + c*8);
                cp16(vb + off, vs + (size_t)r*DD + c*8);
            }
            CP_COMMIT();
        }
    }

    // ---- quad reduce of partial l ----
    lr0 += __shfl_xor_sync(0xffffffffu, lr0, 1);
    lr0 += __shfl_xor_sync(0xffffffffu, lr0, 2);
    lr1 += __shfl_xor_sync(0xffffffffu, lr1, 1);
    lr1 += __shfl_xor_sync(0xffffffffu, lr1, 2);

    // ---- merge khalf partials through smem (reuse K/V region) ----
    CP_WAIT(0);
    __syncthreads();
    char* mg = smem + qg*8256;   // 16 rows x 128 d fp32 (8192B) + 64B l
    if (kh == 1) {
#pragma unroll
        for (int dt=0;dt<16;++dt) {
            *(float2*)(mg + g*512     + (dt*8+t2)*4) = make_float2(o[dt][0], o[dt][1]);
            *(float2*)(mg + (g+8)*512 + (dt*8+t2)*4) = make_float2(o[dt][2], o[dt][3]);
        }
        if ((lane&3)==0) {
            *(float*)(mg + 8192 + g*4)     = lr0;
            *(float*)(mg + 8192 + (g+8)*4) = lr1;
        }
    }
    __syncthreads();
    if (kh == 0) {
        lr0 += *(float*)(mg + 8192 + g*4);
        lr1 += *(float*)(mg + 8192 + (g+8)*4);
        const float inv0 = 1.0f / lr0;
        const float inv1 = 1.0f / lr1;
        float* o0 = out + (qrow0 + (size_t)(qg*16 + g))*DD;
        float* o1 = o0 + 8*DD;
#pragma unroll
        for (int dt=0;dt<16;++dt) {
            float2 a = *(float2*)(mg + g*512     + (dt*8+t2)*4);
            float2 c = *(float2*)(mg + (g+8)*512 + (dt*8+t2)*4);
            *(float2*)(o0 + dt*8 + t2) =
                make_float2((o[dt][0]+a.x)*inv0, (o[dt][1]+a.y)*inv0);
            *(float2*)(o1 + dt*8 + t2) =
                make_float2((o[dt][2]+c.x)*inv1, (o[dt][3]+c.y)*inv1);
        }
    }
}

// ---------------------------------------------------------------------------
extern "C" void kernel_launch(void* const* d_in, const int* in_sizes, int n_in,
                              void* d_out, int out_size)
{
    const float* x  = (const float*)d_in[0];
    const float* Wq = (const float*)d_in[1];
    const float* Wk = (const float*)d_in[2];
    const float* Wv = (const float*)d_in[3];
    float* out = (float*)d_out;

    cudaFuncSetAttribute(proj_mma,
                         cudaFuncAttributeMaxDynamicSharedMemorySize, PJ_SMEM);
    cudaFuncSetAttribute(attn_mma,
                         cudaFuncAttributeMaxDynamicSharedMemorySize, SM_ATTN);

    split_w<<<48, 256>>>(Wq, Wk, Wv);
    proj_mma<<<dim3(256,3), 128, PJ_SMEM>>>(x);
    attn_mma<<<256, 256, SM_ATTN>>>(out);
}

// round 12
// speedup vs baseline: 1.1430x; 1.1430x over previous
#include <cuda_runtime.h>
#include <cuda_fp16.h>
#include <cstdint>

#define BB 4
#define SS 4096
#define DD 128
#define MTOT (BB*SS)

#define BM 64
#define BN 64

// Q scale: 1/sqrt(128) * log2(e)  (softmax uses ex2 directly)
#define QSCALE 0.12751743f

// fp16 scratch
__device__ __half g_qh[MTOT*DD];   // Q, pre-scaled by QSCALE
__device__ __half g_kh[MTOT*DD];   // K
__device__ __half g_vh[MTOT*DD];   // V

// ---------------------------------------------------------------------------
// helpers
// ---------------------------------------------------------------------------
__device__ __forceinline__ uint32_t smem_u32(const void* p) {
    uint32_t a;
    asm("{ .reg .u64 t; cvta.to.shared.u64 t, %1; cvt.u32.u64 %0, t; }"
        : "=r"(a) : "l"(p));
    return a;
}
__device__ __forceinline__ void cp16(uint32_t d, const void* s) {
    asm volatile("cp.async.cg.shared.global [%0], [%1], 16;" :: "r"(d), "l"(s));
}
#define CP_COMMIT() asm volatile("cp.async.commit_group;" ::: "memory")
#define CP_WAIT(N)  asm volatile("cp.async.wait_group %0;" :: "n"(N) : "memory")

__device__ __forceinline__ void ldsm4(uint32_t& r0, uint32_t& r1,
                                      uint32_t& r2, uint32_t& r3, uint32_t a) {
    asm volatile("ldmatrix.sync.aligned.m8n8.x4.shared.b16 {%0,%1,%2,%3},[%4];"
                 : "=r"(r0),"=r"(r1),"=r"(r2),"=r"(r3) : "r"(a));
}
__device__ __forceinline__ void ldsm4t(uint32_t& r0, uint32_t& r1,
                                       uint32_t& r2, uint32_t& r3, uint32_t a) {
    asm volatile("ldmatrix.sync.aligned.m8n8.x4.trans.shared.b16 {%0,%1,%2,%3},[%4];"
                 : "=r"(r0),"=r"(r1),"=r"(r2),"=r"(r3) : "r"(a));
}
__device__ __forceinline__ void mma16816(float* c, const uint32_t* a,
                                         uint32_t b0, uint32_t b1) {
    asm volatile("mma.sync.aligned.m16n8k16.row.col.f32.f16.f16.f32 "
                 "{%0,%1,%2,%3},{%4,%5,%6,%7},{%8,%9},{%0,%1,%2,%3};"
                 : "+f"(c[0]),"+f"(c[1]),"+f"(c[2]),"+f"(c[3])
                 : "r"(a[0]),"r"(a[1]),"r"(a[2]),"r"(a[3]),"r"(b0),"r"(b1));
}
__device__ __forceinline__ uint32_t packh2(float x, float y) {
    __half2 h = __floats2half2_rn(x, y);
    return *(uint32_t*)&h;
}
__device__ __forceinline__ float ex2f(float x) {
    float r;
    asm("ex2.approx.f32 %0, %1;" : "=f"(r) : "f"(x));
    return r;
}
__device__ __forceinline__ void split2(float a, float b, uint32_t& h, uint32_t& l) {
    __half ha = __float2half_rn(a), hb = __float2half_rn(b);
    __half la = __float2half_rn(a - __half2float(ha));
    __half lb = __float2half_rn(b - __half2float(hb));
    __half2 H = __halves2half2(ha, hb), L = __halves2half2(la, lb);
    h = *(uint32_t*)&H; l = *(uint32_t*)&L;
}

// ---------------------------------------------------------------------------
// Kernel 1: QKV projection, 2-term split: y = (x_h + x_l) @ (fp16 W)^T.
// W converted fp32->fp16 inline (no separate split kernel, no W globals).
// grid (256, 3), 128 threads. smem: xh 16K | xl 16K | wh 32K = 64KB.
// ---------------------------------------------------------------------------
#define PJ_XH 0
#define PJ_XL 16384
#define PJ_WH 32768
#define PJ_SMEM 65536

__global__ __launch_bounds__(128) void proj_mma(
    const float* __restrict__ x,
    const float* __restrict__ Wq,
    const float* __restrict__ Wk,
    const float* __restrict__ Wv)
{
    extern __shared__ char smem[];
    const uint32_t sb = smem_u32(smem);
    const int tid = threadIdx.x, wid = tid>>5, lane = tid&31;
    const int m0 = blockIdx.x * 64;
    const int psel = blockIdx.y;
    const float* W = (psel==0) ? Wq : (psel==1) ? Wk : Wv;

    // stage W (128x128 fp32 -> fp16, swizzled)
    for (int i = tid; i < 2048; i += 128) {
        int r = i>>4, c = i&15;
        const float* src = W + (size_t)r*DD + c*8;
        float4 v0 = *(const float4*)src;
        float4 v1 = *(const float4*)(src+4);
        uint4 h;
        h.x = packh2(v0.x, v0.y); h.y = packh2(v0.z, v0.w);
        h.z = packh2(v1.x, v1.y); h.w = packh2(v1.z, v1.w);
        uint32_t off = r*256 + ((c ^ (r&7))<<4);
        *(uint4*)(smem + PJ_WH + off) = h;
    }
    // stage + split x (64x128 fp32)
    for (int i = tid; i < 1024; i += 128) {
        int r = i>>4, c = i&15;
        const float* src = x + (size_t)(m0+r)*DD + c*8;
        float4 v0 = *(const float4*)src;
        float4 v1 = *(const float4*)(src+4);
        uint4 hi, lo;
        split2(v0.x, v0.y, hi.x, lo.x);
        split2(v0.z, v0.w, hi.y, lo.y);
        split2(v1.x, v1.y, hi.z, lo.z);
        split2(v1.z, v1.w, hi.w, lo.w);
        uint32_t off = r*256 + ((c ^ (r&7))<<4);
        *(uint4*)(smem + PJ_XH + off) = hi;
        *(uint4*)(smem + PJ_XL + off) = lo;
    }
    __syncthreads();

    float acc[16][4];
#pragma unroll
    for (int n=0;n<16;++n){ acc[n][0]=acc[n][1]=acc[n][2]=acc[n][3]=0.f; }

    const int arow  = wid*16 + (lane&7) + (((lane>>3)&1)<<3);
    const int achnk = lane>>4;
    const int keyr  = (lane&7) + ((lane>>4)<<3);
    const int kchnk = (lane>>3)&1;

#pragma unroll
    for (int j=0;j<8;++j) {
        uint32_t ah[4], al[4];
        {
            uint32_t cc = 2*j + achnk;
            uint32_t off = arow*256 + ((cc ^ (arow&7))<<4);
            ldsm4(ah[0],ah[1],ah[2],ah[3], sb + PJ_XH + off);
            ldsm4(al[0],al[1],al[2],al[3], sb + PJ_XL + off);
        }
#pragma unroll
        for (int np=0;np<8;++np) {
            int key = np*16 + keyr;
            uint32_t cc = 2*j + kchnk;
            uint32_t off = key*256 + ((cc ^ (key&7))<<4);
            uint32_t b0,b1,b2,b3;
            ldsm4(b0,b1,b2,b3, sb + PJ_WH + off);
            mma16816(acc[2*np],   ah, b0, b1);
            mma16816(acc[2*np+1], ah, b2, b3);
            mma16816(acc[2*np],   al, b0, b1);
            mma16816(acc[2*np+1], al, b2, b3);
        }
    }

    const float sc = (psel==0) ? QSCALE : 1.0f;
    __half* outp = (psel==0) ? g_qh : (psel==1) ? g_kh : g_vh;
    const int g  = lane>>2;
    const int t2 = (lane&3)*2;
    __half* o0 = outp + (size_t)(m0 + wid*16 + g)*DD;
    __half* o1 = o0 + 8*DD;
#pragma unroll
    for (int nt=0; nt<16; ++nt) {
        *(uint32_t*)(o0 + nt*8 + t2) = packh2(acc[nt][0]*sc, acc[nt][1]*sc);
        *(uint32_t*)(o1 + nt*8 + t2) = packh2(acc[nt][2]*sc, acc[nt][3]*sc);
    }
}

// ---------------------------------------------------------------------------
// Kernel 2: fp16 flash attention via mma.sync (no max subtraction, ex2).
// grid = 256, 128 threads, register-resident Q (the R6 winner, reverted).
// blockIdx remapped so co-resident CTA pairs have complementary causal work.
// ---------------------------------------------------------------------------
#define SM_K 0
#define SM_V 32768
#define SM_TOTAL 65536

__global__ __launch_bounds__(128,2) void attn_mma(float* __restrict__ out)
{
    extern __shared__ char smem[];
    const uint32_t sb = smem_u32(smem);
    const int tid = threadIdx.x, wid = tid>>5, lane = tid&31;

    // ---- load-balance remap ----
    const int bid = blockIdx.x;
    int b, qt;
    if (bid < 108)      { qt = 63 - (bid>>2);       b = bid & 3; }
    else if (bid < 148) { qt = 27 + ((bid-108)>>2); b = (bid-108) & 3; }
    else                { qt = (bid-148)>>2;        b = (bid-148) & 3; }

    const int nkt = qt + 1;
    const size_t qrow0 = (size_t)b*SS + (size_t)qt*BM;

    const int g  = lane >> 2;
    const int t2 = (lane & 3) * 2;

    // ---- Q fragments straight from gmem (register resident) ----
    uint32_t qa[8][4];
    {
        const __half* q0 = g_qh + (qrow0 + wid*16 + g)*DD;
#pragma unroll
        for (int j=0;j<8;++j) {
            qa[j][0] = *(const uint32_t*)(q0 + j*16 + t2);
            qa[j][1] = *(const uint32_t*)(q0 + 8*DD + j*16 + t2);
            qa[j][2] = *(const uint32_t*)(q0 + j*16 + t2 + 8);
            qa[j][3] = *(const uint32_t*)(q0 + 8*DD + j*16 + t2 + 8);
        }
    }

    const __half* kbase = g_kh + (size_t)b*SS*DD;
    const __half* vbase = g_vh + (size_t)b*SS*DD;

#pragma unroll 1
    for (int pre=0; pre<2; ++pre) {
        if (pre < nkt) {
            const __half* ks = kbase + (size_t)pre*BN*DD;
            const __half* vs = vbase + (size_t)pre*BN*DD;
            uint32_t kb = sb + SM_K + pre*16384;
            uint32_t vb = sb + SM_V + pre*16384;
            for (int i = tid; i < 1024; i += 128) {
                int r = i>>4, c = i&15;
                uint32_t off = r*256 + ((c ^ (r&7))<<4);
                cp16(kb + off, ks + r*DD + c*8);
                cp16(vb + off, vs + r*DD + c*8);
            }
            CP_COMMIT();
        }
    }

    float o[16][4];
#pragma unroll
    for (int d=0;d<16;++d){ o[d][0]=o[d][1]=o[d][2]=o[d][3]=0.f; }
    float lr0 = 0.f, lr1 = 0.f;

    const int keyr   = (lane&7) + ((lane>>4)<<3);
    const int kchunk = (lane>>3)&1;
    const int vrowr  = (lane&7) + (((lane>>3)&1)<<3);
    const int vchunk = lane>>4;

    for (int kt = 0; kt < nkt; ++kt) {
        const int buf = kt & 1;
        if (kt + 2 <= nkt) { CP_WAIT(1); } else { CP_WAIT(0); }
        __syncthreads();

        const uint32_t kb = sb + SM_K + buf*16384;
        const uint32_t vb = sb + SM_V + buf*16384;

        // ---- S = Q K^T ----
        float s[8][4];
#pragma unroll
        for (int t=0;t<8;++t){ s[t][0]=s[t][1]=s[t][2]=s[t][3]=0.f; }
#pragma unroll
        for (int j=0;j<8;++j) {
#pragma unroll
            for (int tp=0;tp<4;++tp) {
                int key = tp*16 + keyr;
                int cc  = 2*j + kchunk;
                uint32_t addr = kb + key*256 + (((cc ^ (key&7)))<<4);
                uint32_t b0,b1,b2,b3;
                ldsm4(b0,b1,b2,b3, addr);
                mma16816(s[2*tp],   qa[j], b0, b1);
                mma16816(s[2*tp+1], qa[j], b2, b3);
            }
        }

        // ---- softmax: p = 2^s (Q pre-scaled by log2e) ----
        uint32_t pa[4][4];
        const bool diag = (kt == qt);
        const int r0l = wid*16 + g;
#pragma unroll
        for (int t=0;t<8;++t) {
            float v0 = s[t][0], v1 = s[t][1], v2 = s[t][2], v3 = s[t][3];
            if (diag) {
                int kc = t*8 + t2;
                if (kc   > r0l)   v0 = -1e30f;
                if (kc+1 > r0l)   v1 = -1e30f;
                if (kc   > r0l+8) v2 = -1e30f;
                if (kc+1 > r0l+8) v3 = -1e30f;
            }
            float p0 = ex2f(v0), p1 = ex2f(v1), p2 = ex2f(v2), p3 = ex2f(v3);
            lr0 += p0 + p1;
            lr1 += p2 + p3;
            if ((t & 1) == 0) {
                pa[t>>1][0] = packh2(p0,p1);
                pa[t>>1][1] = packh2(p2,p3);
            } else {
                pa[t>>1][2] = packh2(p0,p1);
                pa[t>>1][3] = packh2(p2,p3);
            }
        }

        // ---- O += P V ----
#pragma unroll
        for (int j=0;j<4;++j) {
#pragma unroll
            for (int dp=0;dp<8;++dp) {
                int row = j*16 + vrowr;
                int cc  = dp*2 + vchunk;
                uint32_t addr = vb + row*256 + (((cc ^ (row&7)))<<4);
                uint32_t v0,v1,v2,v3;
                ldsm4t(v0,v1,v2,v3, addr);
                mma16816(o[2*dp],   pa[j], v0, v1);
                mma16816(o[2*dp+1], pa[j], v2, v3);
            }
        }

        __syncthreads();
        if (kt + 2 < nkt) {
            const __half* ks = kbase + (size_t)(kt+2)*BN*DD;
            const __half* vs = vbase + (size_t)(kt+2)*BN*DD;
            for (int i = tid; i < 1024; i += 128) {
                int r = i>>4, c = i&15;
                uint32_t off = r*256 + ((c ^ (r&7))<<4);
                cp16(kb + off, ks + r*DD + c*8);
                cp16(vb + off, vs + r*DD + c*8);
            }
            CP_COMMIT();
        }
    }

    // ---- l reduction across quad ----
    lr0 += __shfl_xor_sync(0xffffffffu, lr0, 1);
    lr0 += __shfl_xor_sync(0xffffffffu, lr0, 2);
    lr1 += __shfl_xor_sync(0xffffffffu, lr1, 1);
    lr1 += __shfl_xor_sync(0xffffffffu, lr1, 2);
    const float inv0 = 1.0f / lr0;
    const float inv1 = 1.0f / lr1;

    float* o0 = out + (qrow0 + wid*16 + g)*DD;
    float* o1 = o0 + 8*DD;
#pragma unroll
    for (int dt=0;dt<16;++dt) {
        *(float2*)(o0 + dt*8 + t2) = make_float2(o[dt][0]*inv0, o[dt][1]*inv0);
        *(float2*)(o1 + dt*8 + t2) = make_float2(o[dt][2]*inv1, o[dt][3]*inv1);
    }
}

// ---------------------------------------------------------------------------
extern "C" void kernel_launch(void* const* d_in, const int* in_sizes, int n_in,
                              void* d_out, int out_size)
{
    const float* x  = (const float*)d_in[0];
    const float* Wq = (const float*)d_in[1];
    const float* Wk = (const float*)d_in[2];
    const float* Wv = (const float*)d_in[3];
    float* out = (float*)d_out;

    cudaFuncSetAttribute(proj_mma,
                         cudaFuncAttributeMaxDynamicSharedMemorySize, PJ_SMEM);
    cudaFuncSetAttribute(attn_mma,
                         cudaFuncAttributeMaxDynamicSharedMemorySize, SM_TOTAL);

    proj_mma<<<dim3(256,3), 128, PJ_SMEM>>>(x, Wq, Wk, Wv);
    attn_mma<<<256, 128, SM_TOTAL>>>(out);
}